// round 14
// baseline (speedup 1.0000x reference)
#include <cuda_runtime.h>
#include <cuda_bf16.h>
#include <stdint.h>

#define IMG   256
#define HW    65536
#define NTOT  131072
#define DIMC  128
#define DWC   256
#define QKVC  768
#define EPSLN 1e-6f

typedef __nv_bfloat16 bf16;

// ---------------- scratch (device globals; no allocations allowed) ----------------
static __device__ bf16  g_hidden[(size_t)QKVC * NTOT];   // 192MB
static __device__ bf16  g_qkv   [(size_t)QKVC * NTOT];   // 192MB
static __device__ bf16  g_attn  [(size_t)DWC  * NTOT];   // 64MB
static __device__ bf16  g_u     [(size_t)DWC  * NTOT];   // 64MB
static __device__ float g_x1    [(size_t)DIMC * NTOT];   // 64MB
static __device__ bf16  g_h2buf [(size_t)DWC  * NTOT];   // 64MB
static __device__ bf16  g_gbuf  [(size_t)DIMC * NTOT];   // 32MB
static __device__ float g_mean[NTOT];
static __device__ float g_rstd[NTOT];
static __device__ float g_W1p[QKVC * DIMC];
static __device__ float g_S1[QKVC];
static __device__ float g_B1[QKVC];
static __device__ float g_W2p[DWC * DIMC];
static __device__ float g_S2[DWC];
static __device__ float g_B2[DWC];

// ---------------- weight folding: W' = W * ln_w, S = rowsum(W'), B = W*ln_b (+bias) ----------------
__global__ void k_prep(const float* __restrict__ w_h1, const float* __restrict__ n1w,
                       const float* __restrict__ n1b,
                       const float* __restrict__ w_h2, const float* __restrict__ b_h2,
                       const float* __restrict__ n3w, const float* __restrict__ n3b)
{
    int o = blockIdx.x * blockDim.x + threadIdx.x;
    if (o < QKVC) {
        float s = 0.f, bb = 0.f;
        for (int c = 0; c < DIMC; c++) {
            float w  = w_h1[o * DIMC + c];
            float wp = w * n1w[c];
            g_W1p[o * DIMC + c] = wp;
            s  += wp;
            bb += w * n1b[c];
        }
        g_S1[o] = s; g_B1[o] = bb;
    } else if (o < QKVC + DWC) {
        int oo = o - QKVC;
        float s = 0.f, bb = b_h2[oo];
        for (int c = 0; c < DIMC; c++) {
            float w  = w_h2[oo * DIMC + c];
            float wp = w * n3w[c];
            g_W2p[oo * DIMC + c] = wp;
            s  += wp;
            bb += w * n3b[c];
        }
        g_S2[oo] = s; g_B2[oo] = bb;
    }
}

// ---------------- per-pixel LN stats (mean, rstd) over channel dim ----------------
__global__ void k_stats(const float* __restrict__ xf, const bf16* __restrict__ xb,
                        int C, int strideC, int bchw)
{
    int n = blockIdx.x * blockDim.x + threadIdx.x;
    size_t base = bchw ? (size_t)(n >> 16) * ((size_t)C * HW) + (size_t)(n & (HW - 1))
                       : (size_t)n;
    float s = 0.f, ss = 0.f;
    if (xf) {
        for (int c = 0; c < C; c++) {
            float v = xf[base + (size_t)c * strideC];
            s += v; ss += v * v;
        }
    } else {
        for (int c = 0; c < C; c++) {
            float v = __bfloat162float(xb[base + (size_t)c * strideC]);
            s += v; ss += v * v;
        }
    }
    float m = s / C;
    g_mean[n] = m;
    g_rstd[n] = rsqrtf(fmaxf(ss / C - m * m, 0.f) + EPSLN);
}

// ---------------- GEMM: out[M,N] = W[M,K] @ A[K,N], 128x128 tile, 8x8/thread ----------------
struct EpiArgs {
    const float* S;      // EPI 0: row sums of folded W
    const float* Bv;     // EPI 0: bias vector
    const float* xin;    // EPI 1/2: residual input
    const float* scale;  // EPI 1/2: per-channel scale
    float*       outF;
    bf16*        outB;
};

template <typename TA, int EPI>
__global__ __launch_bounds__(256, 2)
void k_gemm(const float* __restrict__ W, const TA* __restrict__ A,
            int strideK, int bchwA, int K, EpiArgs ea)
{
    __shared__ float Ws[16][128];
    __shared__ float As[16][128];
    const int tid = threadIdx.x;
    const int tx  = tid & 15;
    const int ty  = tid >> 4;
    const int n0  = blockIdx.x * 128;
    const int m0  = blockIdx.y * 128;
    const size_t abase = bchwA
        ? (size_t)(n0 >> 16) * ((size_t)DIMC * HW) + (size_t)(n0 & (HW - 1))
        : (size_t)n0;
    const float* Wt = W + (size_t)m0 * K;

    float acc[8][8];
#pragma unroll
    for (int r = 0; r < 8; r++)
#pragma unroll
        for (int c = 0; c < 8; c++) acc[r][c] = 0.f;

    for (int k0 = 0; k0 < K; k0 += 16) {
        __syncthreads();
        // W tile 128x16 -> Ws[k][m]
#pragma unroll
        for (int i = 0; i < 2; i++) {
            int f = tid * 2 + i;
            int row = f >> 2;
            int kc  = (f & 3) * 4;
            float4 w4 = *(const float4*)(Wt + (size_t)row * K + (k0 + kc));
            Ws[kc + 0][row] = w4.x;
            Ws[kc + 1][row] = w4.y;
            Ws[kc + 2][row] = w4.z;
            Ws[kc + 3][row] = w4.w;
        }
        // A tile 16x128 -> As[k][n]
        if constexpr (sizeof(TA) == 4) {
#pragma unroll
            for (int i = 0; i < 2; i++) {
                int f = tid * 2 + i;
                int row = f >> 5;
                int c4  = (f & 31) * 4;
                float4 a4 = *(const float4*)((const float*)A + abase +
                                             (size_t)(k0 + row) * strideK + c4);
                *(float4*)&As[row][c4] = a4;
            }
        } else {
            int row = tid >> 4;
            int c8  = (tid & 15) * 8;
            uint4 v = *(const uint4*)((const bf16*)A + abase +
                                      (size_t)(k0 + row) * strideK + c8);
            const __nv_bfloat162* p2 = (const __nv_bfloat162*)&v;
#pragma unroll
            for (int j = 0; j < 4; j++) {
                float2 f2 = __bfloat1622float2(p2[j]);
                As[row][c8 + 2 * j]     = f2.x;
                As[row][c8 + 2 * j + 1] = f2.y;
            }
        }
        __syncthreads();
#pragma unroll
        for (int kk = 0; kk < 16; kk++) {
            float wr[8], ar[8];
            float4 t;
            t = *(const float4*)&Ws[kk][ty * 4];      wr[0]=t.x; wr[1]=t.y; wr[2]=t.z; wr[3]=t.w;
            t = *(const float4*)&Ws[kk][64 + ty * 4]; wr[4]=t.x; wr[5]=t.y; wr[6]=t.z; wr[7]=t.w;
            t = *(const float4*)&As[kk][tx * 4];      ar[0]=t.x; ar[1]=t.y; ar[2]=t.z; ar[3]=t.w;
            t = *(const float4*)&As[kk][64 + tx * 4]; ar[4]=t.x; ar[5]=t.y; ar[6]=t.z; ar[7]=t.w;
#pragma unroll
            for (int r = 0; r < 8; r++)
#pragma unroll
                for (int c = 0; c < 8; c++)
                    acc[r][c] = fmaf(wr[r], ar[c], acc[r][c]);
        }
    }

    int mrow[8], ncol[8];
#pragma unroll
    for (int r = 0; r < 4; r++) { mrow[r] = ty * 4 + r; mrow[r + 4] = 64 + ty * 4 + r; }
#pragma unroll
    for (int c = 0; c < 4; c++) { ncol[c] = tx * 4 + c; ncol[c + 4] = 64 + tx * 4 + c; }

    if constexpr (EPI == 0) {
        // LN-folded epilogue -> bf16 (C,N) buffer
        float mn[8], rn[8];
#pragma unroll
        for (int c = 0; c < 8; c++) {
            int n = n0 + ncol[c];
            mn[c] = g_mean[n];
            rn[c] = g_rstd[n];
        }
#pragma unroll
        for (int r = 0; r < 8; r++) {
            int m = m0 + mrow[r];
            float Sv  = ea.S[m];
            float Bvv = ea.Bv[m];
            size_t ro = (size_t)m * NTOT + n0;
#pragma unroll
            for (int c = 0; c < 8; c += 2) {
                __nv_bfloat162 t2;
                t2.x = __float2bfloat16(rn[c]     * (acc[r][c]     - mn[c]     * Sv) + Bvv);
                t2.y = __float2bfloat16(rn[c + 1] * (acc[r][c + 1] - mn[c + 1] * Sv) + Bvv);
                *(__nv_bfloat162*)(ea.outB + ro + ncol[c]) = t2;
            }
        }
    } else if constexpr (EPI == 1) {
        // x1 = x(BCHW) + acc*scale -> f32 (C,N)
#pragma unroll
        for (int r = 0; r < 8; r++) {
            int m = m0 + mrow[r];
            float sc = ea.scale[m];
#pragma unroll
            for (int c = 0; c < 8; c++) {
                int n = n0 + ncol[c];
                float xv = ea.xin[(size_t)(n >> 16) * ((size_t)DIMC * HW) +
                                  (size_t)m * HW + (n & (HW - 1))];
                ea.outF[(size_t)m * NTOT + n] = xv + acc[r][c] * sc;
            }
        }
    } else {
        // out(BCHW) = x1(C,N) + acc*scale
#pragma unroll
        for (int r = 0; r < 8; r++) {
            int m = m0 + mrow[r];
            float sc = ea.scale[m];
#pragma unroll
            for (int c = 0; c < 8; c++) {
                int n = n0 + ncol[c];
                float xv = ea.xin[(size_t)m * NTOT + n];
                ea.outF[(size_t)(n >> 16) * ((size_t)DIMC * HW) +
                        (size_t)m * HW + (n & (HW - 1))] = xv + acc[r][c] * sc;
            }
        }
    }
}

// ---------------- depthwise 3x3, SAME/zero-pad, (C,B,HW) bf16 ----------------
__global__ __launch_bounds__(256)
void k_dwconv(const bf16* __restrict__ in, bf16* __restrict__ out,
              const float* __restrict__ w)
{
    __shared__ float s[10][34];
    int c  = blockIdx.z >> 1, b = blockIdx.z & 1;
    int x0 = blockIdx.x * 32, y0 = blockIdx.y * 8;
    size_t base = (size_t)c * NTOT + (size_t)b * HW;
    int tid = threadIdx.x;
    for (int i = tid; i < 340; i += 256) {
        int r = i / 34, cc = i % 34;
        int gy = y0 - 1 + r, gx = x0 - 1 + cc;
        float v = 0.f;
        if (gy >= 0 && gy < IMG && gx >= 0 && gx < IMG)
            v = __bfloat162float(in[base + (size_t)gy * IMG + gx]);
        s[r][cc] = v;
    }
    __syncthreads();
    const float* wc = w + c * 9;
    int x = tid & 31, y = tid >> 5;
    float a =
        wc[0]*s[y][x]     + wc[1]*s[y][x+1]     + wc[2]*s[y][x+2] +
        wc[3]*s[y+1][x]   + wc[4]*s[y+1][x+1]   + wc[5]*s[y+1][x+2] +
        wc[6]*s[y+2][x]   + wc[7]*s[y+2][x+1]   + wc[8]*s[y+2][x+2];
    out[base + (size_t)(y0 + y) * IMG + (x0 + x)] = __float2bfloat16(a);
}

// ---------------- FFN: depthwise 3x3 on both halves + GLU product ----------------
__global__ __launch_bounds__(256)
void k_dwconv_glu(const bf16* __restrict__ in, bf16* __restrict__ out,
                  const float* __restrict__ w)
{
    __shared__ float s1[10][34];
    __shared__ float s2[10][34];
    int c  = blockIdx.z >> 1, b = blockIdx.z & 1;
    int x0 = blockIdx.x * 32, y0 = blockIdx.y * 8;
    size_t base1 = (size_t)c * NTOT + (size_t)b * HW;
    size_t base2 = (size_t)(c + DIMC) * NTOT + (size_t)b * HW;
    int tid = threadIdx.x;
    for (int i = tid; i < 340; i += 256) {
        int r = i / 34, cc = i % 34;
        int gy = y0 - 1 + r, gx = x0 - 1 + cc;
        float v1 = 0.f, v2 = 0.f;
        if (gy >= 0 && gy < IMG && gx >= 0 && gx < IMG) {
            size_t o = (size_t)gy * IMG + gx;
            v1 = __bfloat162float(in[base1 + o]);
            v2 = __bfloat162float(in[base2 + o]);
        }
        s1[r][cc] = v1; s2[r][cc] = v2;
    }
    __syncthreads();
    const float* w1 = w + c * 9;
    const float* w2 = w + (c + DIMC) * 9;
    int x = tid & 31, y = tid >> 5;
    float a1 =
        w1[0]*s1[y][x]   + w1[1]*s1[y][x+1]   + w1[2]*s1[y][x+2] +
        w1[3]*s1[y+1][x] + w1[4]*s1[y+1][x+1] + w1[5]*s1[y+1][x+2] +
        w1[6]*s1[y+2][x] + w1[7]*s1[y+2][x+1] + w1[8]*s1[y+2][x+2];
    float a2 =
        w2[0]*s2[y][x]   + w2[1]*s2[y][x+1]   + w2[2]*s2[y][x+2] +
        w2[3]*s2[y+1][x] + w2[4]*s2[y+1][x+1] + w2[5]*s2[y+1][x+2] +
        w2[6]*s2[y+2][x] + w2[7]*s2[y+2][x+1] + w2[8]*s2[y+2][x+2];
    out[base1 + (size_t)(y0 + y) * IMG + (x0 + x)] = __float2bfloat16(a1 * a2);
}

// ---------------- per-8x8-patch circular convolution attn = q (*) k ----------------
__global__ __launch_bounds__(256)
void k_attn(const bf16* __restrict__ qkv, bf16* __restrict__ attn)
{
    __shared__ float sQ[32][8][8];
    __shared__ float sK[32][8][8];
    int tid = threadIdx.x;
    int pl  = tid >> 3, yr = tid & 7;
    int gp  = blockIdx.x * 32 + pl;       // global patch unit: (c,b,py,px)
    int c   = gp >> 11;
    int rem = gp & 2047;
    int b   = rem >> 10;
    int p   = rem & 1023;
    int py  = p >> 5, px = p & 31;
    size_t pix = (size_t)b * HW + (size_t)(py * 8 + yr) * IMG + (size_t)px * 8;
    {
        uint4 qv = *(const uint4*)(qkv + (size_t)c * NTOT + pix);
        uint4 kv = *(const uint4*)(qkv + (size_t)(c + DWC) * NTOT + pix);
        const __nv_bfloat162* qp = (const __nv_bfloat162*)&qv;
        const __nv_bfloat162* kp = (const __nv_bfloat162*)&kv;
#pragma unroll
        for (int j = 0; j < 4; j++) {
            float2 f = __bfloat1622float2(qp[j]);
            sQ[pl][yr][2 * j] = f.x; sQ[pl][yr][2 * j + 1] = f.y;
            f = __bfloat1622float2(kp[j]);
            sK[pl][yr][2 * j] = f.x; sK[pl][yr][2 * j + 1] = f.y;
        }
    }
    __syncthreads();
    float acc[8];
#pragma unroll
    for (int xx = 0; xx < 8; xx++) acc[xx] = 0.f;
#pragma unroll
    for (int u = 0; u < 8; u++) {
        int krow = (yr - u) & 7;
        float qr[8], kr[8];
#pragma unroll
        for (int j = 0; j < 8; j++) qr[j] = sQ[pl][u][j];
#pragma unroll
        for (int j = 0; j < 8; j++) kr[j] = sK[pl][krow][j];
#pragma unroll
        for (int v = 0; v < 8; v++)
#pragma unroll
            for (int xx = 0; xx < 8; xx++)
                acc[xx] = fmaf(qr[v], kr[(xx - v) & 7], acc[xx]);
    }
    uint4 ov;
    __nv_bfloat162* op = (__nv_bfloat162*)&ov;
#pragma unroll
    for (int j = 0; j < 4; j++) {
        __nv_bfloat162 t;
        t.x = __float2bfloat16(acc[2 * j]);
        t.y = __float2bfloat16(acc[2 * j + 1]);
        op[j] = t;
    }
    *(uint4*)(attn + (size_t)c * NTOT + pix) = ov;
}

// ---------------- u = v * LN2(attn) ----------------
__global__ __launch_bounds__(256)
void k_mulv(const bf16* __restrict__ vv, const bf16* __restrict__ at,
            bf16* __restrict__ uo,
            const float* __restrict__ w2, const float* __restrict__ b2)
{
    size_t idx = ((size_t)blockIdx.x * 256 + threadIdx.x) * 8;
    int c = (int)(idx >> 17);           // / NTOT (2^17)
    int n = (int)(idx & (NTOT - 1));
    float wc = w2[c], bc = b2[c];
    uint4 av  = *(const uint4*)(at + idx);
    uint4 vv4 = *(const uint4*)(vv + idx);
    float4 m0 = *(const float4*)&g_mean[n];
    float4 m1 = *(const float4*)&g_mean[n + 4];
    float4 r0 = *(const float4*)&g_rstd[n];
    float4 r1 = *(const float4*)&g_rstd[n + 4];
    float mm[8] = {m0.x, m0.y, m0.z, m0.w, m1.x, m1.y, m1.z, m1.w};
    float rr[8] = {r0.x, r0.y, r0.z, r0.w, r1.x, r1.y, r1.z, r1.w};
    const __nv_bfloat162* ap = (const __nv_bfloat162*)&av;
    const __nv_bfloat162* vp = (const __nv_bfloat162*)&vv4;
    uint4 ov;
    __nv_bfloat162* op = (__nv_bfloat162*)&ov;
#pragma unroll
    for (int j = 0; j < 4; j++) {
        float2 a2 = __bfloat1622float2(ap[j]);
        float2 v2 = __bfloat1622float2(vp[j]);
        float u0 = v2.x * ((a2.x - mm[2 * j])     * rr[2 * j]     * wc + bc);
        float u1 = v2.y * ((a2.y - mm[2 * j + 1]) * rr[2 * j + 1] * wc + bc);
        __nv_bfloat162 t;
        t.x = __float2bfloat16(u0);
        t.y = __float2bfloat16(u1);
        op[j] = t;
    }
    *(uint4*)(uo + idx) = ov;
}

// ---------------- launch ----------------
extern "C" void kernel_launch(void* const* d_in, const int* in_sizes, int n_in,
                              void* d_out, int out_size)
{
    const float* x      = (const float*)d_in[0];
    const float* n1w    = (const float*)d_in[1];
    const float* n1b    = (const float*)d_in[2];
    const float* w_h1   = (const float*)d_in[3];
    const float* w_dw1  = (const float*)d_in[4];
    const float* n2w    = (const float*)d_in[5];
    const float* n2b    = (const float*)d_in[6];
    const float* w_p1   = (const float*)d_in[7];
    const float* n3w    = (const float*)d_in[8];
    const float* n3b    = (const float*)d_in[9];
    const float* w_h2   = (const float*)d_in[10];
    const float* b_h2   = (const float*)d_in[11];
    const float* w_dw2  = (const float*)d_in[12];
    const float* w_p2   = (const float*)d_in[13];
    const float* scale1 = (const float*)d_in[14];
    const float* scale2 = (const float*)d_in[15];

    void *p_hidden, *p_qkv, *p_attn, *p_u, *p_x1, *p_h2, *p_g;
    void *p_W1p, *p_S1, *p_B1, *p_W2p, *p_S2, *p_B2;
    cudaGetSymbolAddress(&p_hidden, g_hidden);
    cudaGetSymbolAddress(&p_qkv,    g_qkv);
    cudaGetSymbolAddress(&p_attn,   g_attn);
    cudaGetSymbolAddress(&p_u,      g_u);
    cudaGetSymbolAddress(&p_x1,     g_x1);
    cudaGetSymbolAddress(&p_h2,     g_h2buf);
    cudaGetSymbolAddress(&p_g,      g_gbuf);
    cudaGetSymbolAddress(&p_W1p,    g_W1p);
    cudaGetSymbolAddress(&p_S1,     g_S1);
    cudaGetSymbolAddress(&p_B1,     g_B1);
    cudaGetSymbolAddress(&p_W2p,    g_W2p);
    cudaGetSymbolAddress(&p_S2,     g_S2);
    cudaGetSymbolAddress(&p_B2,     g_B2);

    // 1) fold LN weights into GEMM weights
    k_prep<<<8, 128>>>(w_h1, n1w, n1b, w_h2, b_h2, n3w, n3b);
    // 2) LN1 stats on x
    k_stats<<<NTOT / 256, 256>>>(x, nullptr, DIMC, HW, 1);
    // 3) GEMM1 (768x128) with LN epilogue -> hidden
    {
        EpiArgs e = {};
        e.S = (const float*)p_S1; e.Bv = (const float*)p_B1; e.outB = (bf16*)p_hidden;
        k_gemm<float, 0><<<dim3(NTOT / 128, QKVC / 128), 256>>>(
            (const float*)p_W1p, x, HW, 1, DIMC, e);
    }
    // 4) depthwise 3x3 -> qkv
    k_dwconv<<<dim3(IMG / 32, IMG / 8, QKVC * 2), 256>>>(
        (const bf16*)p_hidden, (bf16*)p_qkv, w_dw1);
    // 5) patch circular conv -> attn
    k_attn<<<(2 * DWC * 1024) / 32, 256>>>((const bf16*)p_qkv, (bf16*)p_attn);
    // 6) LN2 stats on attn
    k_stats<<<NTOT / 256, 256>>>(nullptr, (const bf16*)p_attn, DWC, NTOT, 0);
    // 7) u = v * LN2(attn)
    k_mulv<<<(unsigned)(((size_t)DWC * NTOT) / 8 / 256), 256>>>(
        (const bf16*)p_qkv + (size_t)2 * DWC * NTOT, (const bf16*)p_attn,
        (bf16*)p_u, n2w, n2b);
    // 8) GEMM p1 (128x256), epilogue x1 = x + out*scale1
    {
        EpiArgs e = {};
        e.xin = x; e.scale = scale1; e.outF = (float*)p_x1;
        k_gemm<bf16, 1><<<dim3(NTOT / 128, 1), 256>>>(
            w_p1, (const bf16*)p_u, NTOT, 0, DWC, e);
    }
    // 9) LN3 stats on x1
    k_stats<<<NTOT / 256, 256>>>((const float*)p_x1, nullptr, DIMC, NTOT, 0);
    // 10) GEMM h2 (256x128) with LN epilogue (+bias) -> h2
    {
        EpiArgs e = {};
        e.S = (const float*)p_S2; e.Bv = (const float*)p_B2; e.outB = (bf16*)p_h2;
        k_gemm<float, 0><<<dim3(NTOT / 128, DWC / 128), 256>>>(
            (const float*)p_W2p, (const float*)p_x1, NTOT, 0, DIMC, e);
    }
    // 11) depthwise 3x3 on both halves + GLU product -> g
    k_dwconv_glu<<<dim3(IMG / 32, IMG / 8, DIMC * 2), 256>>>(
        (const bf16*)p_h2, (bf16*)p_g, w_dw2);
    // 12) GEMM p2 (128x128), epilogue out = x1 + out*scale2 -> d_out (BCHW)
    {
        EpiArgs e = {};
        e.xin = (const float*)p_x1; e.scale = scale2; e.outF = (float*)d_out;
        k_gemm<bf16, 2><<<dim3(NTOT / 128, 1), 256>>>(
            w_p2, (const bf16*)p_g, NTOT, 0, DIMC, e);
    }
}

// round 15
// speedup vs baseline: 1.0056x; 1.0056x over previous
#include <cuda_runtime.h>
#include <cuda_bf16.h>
#include <stdint.h>

#define IMG   256
#define HW    65536
#define NTOT  131072
#define DIMC  128
#define DWC   256
#define QKVC  768
#define EPSLN 1e-6f

typedef __nv_bfloat16 bf16;

// ---------------- scratch (device globals; no allocations allowed) ----------------
static __device__ bf16  g_hidden[(size_t)QKVC * NTOT];   // 192MB
static __device__ bf16  g_qkv   [(size_t)QKVC * NTOT];   // 192MB
static __device__ bf16  g_attn  [(size_t)DWC  * NTOT];   // 64MB
static __device__ bf16  g_u     [(size_t)DWC  * NTOT];   // 64MB
static __device__ float g_x1    [(size_t)DIMC * NTOT];   // 64MB
static __device__ bf16  g_h2buf [(size_t)DWC  * NTOT];   // 64MB
static __device__ bf16  g_gbuf  [(size_t)DIMC * NTOT];   // 32MB
static __device__ float g_mean[NTOT];
static __device__ float g_rstd[NTOT];
static __device__ float g_W1p[QKVC * DIMC];
static __device__ float g_S1[QKVC];
static __device__ float g_B1[QKVC];
static __device__ float g_W2p[DWC * DIMC];
static __device__ float g_S2[DWC];
static __device__ float g_B2[DWC];

// ---------------- weight folding: W' = W * ln_w, S = rowsum(W'), B = W*ln_b (+bias) ----------------
__global__ void k_prep(const float* __restrict__ w_h1, const float* __restrict__ n1w,
                       const float* __restrict__ n1b,
                       const float* __restrict__ w_h2, const float* __restrict__ b_h2,
                       const float* __restrict__ n3w, const float* __restrict__ n3b)
{
    int o = blockIdx.x * blockDim.x + threadIdx.x;
    if (o < QKVC) {
        float s = 0.f, bb = 0.f;
        for (int c = 0; c < DIMC; c++) {
            float w  = w_h1[o * DIMC + c];
            float wp = w * n1w[c];
            g_W1p[o * DIMC + c] = wp;
            s  += wp;
            bb += w * n1b[c];
        }
        g_S1[o] = s; g_B1[o] = bb;
    } else if (o < QKVC + DWC) {
        int oo = o - QKVC;
        float s = 0.f, bb = b_h2[oo];
        for (int c = 0; c < DIMC; c++) {
            float w  = w_h2[oo * DIMC + c];
            float wp = w * n3w[c];
            g_W2p[oo * DIMC + c] = wp;
            s  += wp;
            bb += w * n3b[c];
        }
        g_S2[oo] = s; g_B2[oo] = bb;
    }
}

// ---------------- per-pixel LN stats (mean, rstd) over channel dim ----------------
__global__ void k_stats(const float* __restrict__ xf, const bf16* __restrict__ xb,
                        int C, int strideC, int bchw)
{
    int n = blockIdx.x * blockDim.x + threadIdx.x;
    size_t base = bchw ? (size_t)(n >> 16) * ((size_t)C * HW) + (size_t)(n & (HW - 1))
                       : (size_t)n;
    float s = 0.f, ss = 0.f;
    if (xf) {
        for (int c = 0; c < C; c++) {
            float v = xf[base + (size_t)c * strideC];
            s += v; ss += v * v;
        }
    } else {
        for (int c = 0; c < C; c++) {
            float v = __bfloat162float(xb[base + (size_t)c * strideC]);
            s += v; ss += v * v;
        }
    }
    float m = s / C;
    g_mean[n] = m;
    g_rstd[n] = rsqrtf(fmaxf(ss / C - m * m, 0.f) + EPSLN);
}

// ---------------- GEMM: out[M,N] = W[M,K] @ A[K,N], 128x128 tile, 8x8/thread ----------------
struct EpiArgs {
    const float* S;      // EPI 0: row sums of folded W
    const float* Bv;     // EPI 0: bias vector
    const float* xin;    // EPI 1/2: residual input
    const float* scale;  // EPI 1/2: per-channel scale
    float*       outF;
    bf16*        outB;
};

template <typename TA, int EPI>
__global__ __launch_bounds__(256, 2)
void k_gemm(const float* __restrict__ W, const TA* __restrict__ A,
            int strideK, int bchwA, int K, EpiArgs ea)
{
    __shared__ float Ws[16][128];
    __shared__ float As[16][128];
    const int tid = threadIdx.x;
    const int tx  = tid & 15;
    const int ty  = tid >> 4;
    const int n0  = blockIdx.x * 128;
    const int m0  = blockIdx.y * 128;
    const size_t abase = bchwA
        ? (size_t)(n0 >> 16) * ((size_t)DIMC * HW) + (size_t)(n0 & (HW - 1))
        : (size_t)n0;
    const float* Wt = W + (size_t)m0 * K;

    float acc[8][8];
#pragma unroll
    for (int r = 0; r < 8; r++)
#pragma unroll
        for (int c = 0; c < 8; c++) acc[r][c] = 0.f;

    for (int k0 = 0; k0 < K; k0 += 16) {
        __syncthreads();
        // W tile 128x16 -> Ws[k][m]
#pragma unroll
        for (int i = 0; i < 2; i++) {
            int f = tid * 2 + i;
            int row = f >> 2;
            int kc  = (f & 3) * 4;
            float4 w4 = *(const float4*)(Wt + (size_t)row * K + (k0 + kc));
            Ws[kc + 0][row] = w4.x;
            Ws[kc + 1][row] = w4.y;
            Ws[kc + 2][row] = w4.z;
            Ws[kc + 3][row] = w4.w;
        }
        // A tile 16x128 -> As[k][n]
        if constexpr (sizeof(TA) == 4) {
#pragma unroll
            for (int i = 0; i < 2; i++) {
                int f = tid * 2 + i;
                int row = f >> 5;
                int c4  = (f & 31) * 4;
                float4 a4 = *(const float4*)((const float*)A + abase +
                                             (size_t)(k0 + row) * strideK + c4);
                *(float4*)&As[row][c4] = a4;
            }
        } else {
            int row = tid >> 4;
            int c8  = (tid & 15) * 8;
            uint4 v = *(const uint4*)((const bf16*)A + abase +
                                      (size_t)(k0 + row) * strideK + c8);
            const __nv_bfloat162* p2 = (const __nv_bfloat162*)&v;
#pragma unroll
            for (int j = 0; j < 4; j++) {
                float2 f2 = __bfloat1622float2(p2[j]);
                As[row][c8 + 2 * j]     = f2.x;
                As[row][c8 + 2 * j + 1] = f2.y;
            }
        }
        __syncthreads();
#pragma unroll
        for (int kk = 0; kk < 16; kk++) {
            float wr[8], ar[8];
            float4 t;
            t = *(const float4*)&Ws[kk][ty * 4];      wr[0]=t.x; wr[1]=t.y; wr[2]=t.z; wr[3]=t.w;
            t = *(const float4*)&Ws[kk][64 + ty * 4]; wr[4]=t.x; wr[5]=t.y; wr[6]=t.z; wr[7]=t.w;
            t = *(const float4*)&As[kk][tx * 4];      ar[0]=t.x; ar[1]=t.y; ar[2]=t.z; ar[3]=t.w;
            t = *(const float4*)&As[kk][64 + tx * 4]; ar[4]=t.x; ar[5]=t.y; ar[6]=t.z; ar[7]=t.w;
#pragma unroll
            for (int r = 0; r < 8; r++)
#pragma unroll
                for (int c = 0; c < 8; c++)
                    acc[r][c] = fmaf(wr[r], ar[c], acc[r][c]);
        }
    }

    int mrow[8], ncol[8];
#pragma unroll
    for (int r = 0; r < 4; r++) { mrow[r] = ty * 4 + r; mrow[r + 4] = 64 + ty * 4 + r; }
#pragma unroll
    for (int c = 0; c < 4; c++) { ncol[c] = tx * 4 + c; ncol[c + 4] = 64 + tx * 4 + c; }

    if constexpr (EPI == 0) {
        // LN-folded epilogue -> bf16 (C,N) buffer
        float mn[8], rn[8];
#pragma unroll
        for (int c = 0; c < 8; c++) {
            int n = n0 + ncol[c];
            mn[c] = g_mean[n];
            rn[c] = g_rstd[n];
        }
#pragma unroll
        for (int r = 0; r < 8; r++) {
            int m = m0 + mrow[r];
            float Sv  = ea.S[m];
            float Bvv = ea.Bv[m];
            size_t ro = (size_t)m * NTOT + n0;
#pragma unroll
            for (int c = 0; c < 8; c += 2) {
                __nv_bfloat162 t2;
                t2.x = __float2bfloat16(rn[c]     * (acc[r][c]     - mn[c]     * Sv) + Bvv);
                t2.y = __float2bfloat16(rn[c + 1] * (acc[r][c + 1] - mn[c + 1] * Sv) + Bvv);
                *(__nv_bfloat162*)(ea.outB + ro + ncol[c]) = t2;
            }
        }
    } else if constexpr (EPI == 1) {
        // x1 = x(BCHW) + acc*scale -> f32 (C,N)
#pragma unroll
        for (int r = 0; r < 8; r++) {
            int m = m0 + mrow[r];
            float sc = ea.scale[m];
#pragma unroll
            for (int c = 0; c < 8; c++) {
                int n = n0 + ncol[c];
                float xv = ea.xin[(size_t)(n >> 16) * ((size_t)DIMC * HW) +
                                  (size_t)m * HW + (n & (HW - 1))];
                ea.outF[(size_t)m * NTOT + n] = xv + acc[r][c] * sc;
            }
        }
    } else {
        // out(BCHW) = x1(C,N) + acc*scale
#pragma unroll
        for (int r = 0; r < 8; r++) {
            int m = m0 + mrow[r];
            float sc = ea.scale[m];
#pragma unroll
            for (int c = 0; c < 8; c++) {
                int n = n0 + ncol[c];
                float xv = ea.xin[(size_t)m * NTOT + n];
                ea.outF[(size_t)(n >> 16) * ((size_t)DIMC * HW) +
                        (size_t)m * HW + (n & (HW - 1))] = xv + acc[r][c] * sc;
            }
        }
    }
}

// ---------------- depthwise 3x3, SAME/zero-pad, (C,B,HW) bf16 ----------------
__global__ __launch_bounds__(256)
void k_dwconv(const bf16* __restrict__ in, bf16* __restrict__ out,
              const float* __restrict__ w)
{
    __shared__ float s[10][34];
    int c  = blockIdx.z >> 1, b = blockIdx.z & 1;
    int x0 = blockIdx.x * 32, y0 = blockIdx.y * 8;
    size_t base = (size_t)c * NTOT + (size_t)b * HW;
    int tid = threadIdx.x;
    for (int i = tid; i < 340; i += 256) {
        int r = i / 34, cc = i % 34;
        int gy = y0 - 1 + r, gx = x0 - 1 + cc;
        float v = 0.f;
        if (gy >= 0 && gy < IMG && gx >= 0 && gx < IMG)
            v = __bfloat162float(in[base + (size_t)gy * IMG + gx]);
        s[r][cc] = v;
    }
    __syncthreads();
    const float* wc = w + c * 9;
    int x = tid & 31, y = tid >> 5;
    float a =
        wc[0]*s[y][x]     + wc[1]*s[y][x+1]     + wc[2]*s[y][x+2] +
        wc[3]*s[y+1][x]   + wc[4]*s[y+1][x+1]   + wc[5]*s[y+1][x+2] +
        wc[6]*s[y+2][x]   + wc[7]*s[y+2][x+1]   + wc[8]*s[y+2][x+2];
    out[base + (size_t)(y0 + y) * IMG + (x0 + x)] = __float2bfloat16(a);
}

// ---------------- FFN: depthwise 3x3 on both halves + GLU product ----------------
__global__ __launch_bounds__(256)
void k_dwconv_glu(const bf16* __restrict__ in, bf16* __restrict__ out,
                  const float* __restrict__ w)
{
    __shared__ float s1[10][34];
    __shared__ float s2[10][34];
    int c  = blockIdx.z >> 1, b = blockIdx.z & 1;
    int x0 = blockIdx.x * 32, y0 = blockIdx.y * 8;
    size_t base1 = (size_t)c * NTOT + (size_t)b * HW;
    size_t base2 = (size_t)(c + DIMC) * NTOT + (size_t)b * HW;
    int tid = threadIdx.x;
    for (int i = tid; i < 340; i += 256) {
        int r = i / 34, cc = i % 34;
        int gy = y0 - 1 + r, gx = x0 - 1 + cc;
        float v1 = 0.f, v2 = 0.f;
        if (gy >= 0 && gy < IMG && gx >= 0 && gx < IMG) {
            size_t o = (size_t)gy * IMG + gx;
            v1 = __bfloat162float(in[base1 + o]);
            v2 = __bfloat162float(in[base2 + o]);
        }
        s1[r][cc] = v1; s2[r][cc] = v2;
    }
    __syncthreads();
    const float* w1 = w + c * 9;
    const float* w2 = w + (c + DIMC) * 9;
    int x = tid & 31, y = tid >> 5;
    float a1 =
        w1[0]*s1[y][x]   + w1[1]*s1[y][x+1]   + w1[2]*s1[y][x+2] +
        w1[3]*s1[y+1][x] + w1[4]*s1[y+1][x+1] + w1[5]*s1[y+1][x+2] +
        w1[6]*s1[y+2][x] + w1[7]*s1[y+2][x+1] + w1[8]*s1[y+2][x+2];
    float a2 =
        w2[0]*s2[y][x]   + w2[1]*s2[y][x+1]   + w2[2]*s2[y][x+2] +
        w2[3]*s2[y+1][x] + w2[4]*s2[y+1][x+1] + w2[5]*s2[y+1][x+2] +
        w2[6]*s2[y+2][x] + w2[7]*s2[y+2][x+1] + w2[8]*s2[y+2][x+2];
    out[base1 + (size_t)(y0 + y) * IMG + (x0 + x)] = __float2bfloat16(a1 * a2);
}

// ---------------- per-8x8-patch circular convolution attn = q (*) k ----------------
__global__ __launch_bounds__(256)
void k_attn(const bf16* __restrict__ qkv, bf16* __restrict__ attn)
{
    __shared__ float sQ[32][8][8];
    __shared__ float sK[32][8][8];
    int tid = threadIdx.x;
    int pl  = tid >> 3, yr = tid & 7;
    int gp  = blockIdx.x * 32 + pl;       // global patch unit: (c,b,py,px)
    int c   = gp >> 11;
    int rem = gp & 2047;
    int b   = rem >> 10;
    int p   = rem & 1023;
    int py  = p >> 5, px = p & 31;
    size_t pix = (size_t)b * HW + (size_t)(py * 8 + yr) * IMG + (size_t)px * 8;
    {
        uint4 qv = *(const uint4*)(qkv + (size_t)c * NTOT + pix);
        uint4 kv = *(const uint4*)(qkv + (size_t)(c + DWC) * NTOT + pix);
        const __nv_bfloat162* qp = (const __nv_bfloat162*)&qv;
        const __nv_bfloat162* kp = (const __nv_bfloat162*)&kv;
#pragma unroll
        for (int j = 0; j < 4; j++) {
            float2 f = __bfloat1622float2(qp[j]);
            sQ[pl][yr][2 * j] = f.x; sQ[pl][yr][2 * j + 1] = f.y;
            f = __bfloat1622float2(kp[j]);
            sK[pl][yr][2 * j] = f.x; sK[pl][yr][2 * j + 1] = f.y;
        }
    }
    __syncthreads();
    float acc[8];
#pragma unroll
    for (int xx = 0; xx < 8; xx++) acc[xx] = 0.f;
#pragma unroll
    for (int u = 0; u < 8; u++) {
        int krow = (yr - u) & 7;
        float qr[8], kr[8];
#pragma unroll
        for (int j = 0; j < 8; j++) qr[j] = sQ[pl][u][j];
#pragma unroll
        for (int j = 0; j < 8; j++) kr[j] = sK[pl][krow][j];
#pragma unroll
        for (int v = 0; v < 8; v++)
#pragma unroll
            for (int xx = 0; xx < 8; xx++)
                acc[xx] = fmaf(qr[v], kr[(xx - v) & 7], acc[xx]);
    }
    uint4 ov;
    __nv_bfloat162* op = (__nv_bfloat162*)&ov;
#pragma unroll
    for (int j = 0; j < 4; j++) {
        __nv_bfloat162 t;
        t.x = __float2bfloat16(acc[2 * j]);
        t.y = __float2bfloat16(acc[2 * j + 1]);
        op[j] = t;
    }
    *(uint4*)(attn + (size_t)c * NTOT + pix) = ov;
}

// ---------------- u = v * LN2(attn) ----------------
__global__ __launch_bounds__(256)
void k_mulv(const bf16* __restrict__ vv, const bf16* __restrict__ at,
            bf16* __restrict__ uo,
            const float* __restrict__ w2, const float* __restrict__ b2)
{
    size_t idx = ((size_t)blockIdx.x * 256 + threadIdx.x) * 8;
    int c = (int)(idx >> 17);           // / NTOT (2^17)
    int n = (int)(idx & (NTOT - 1));
    float wc = w2[c], bc = b2[c];
    uint4 av  = *(const uint4*)(at + idx);
    uint4 vv4 = *(const uint4*)(vv + idx);
    float4 m0 = *(const float4*)&g_mean[n];
    float4 m1 = *(const float4*)&g_mean[n + 4];
    float4 r0 = *(const float4*)&g_rstd[n];
    float4 r1 = *(const float4*)&g_rstd[n + 4];
    float mm[8] = {m0.x, m0.y, m0.z, m0.w, m1.x, m1.y, m1.z, m1.w};
    float rr[8] = {r0.x, r0.y, r0.z, r0.w, r1.x, r1.y, r1.z, r1.w};
    const __nv_bfloat162* ap = (const __nv_bfloat162*)&av;
    const __nv_bfloat162* vp = (const __nv_bfloat162*)&vv4;
    uint4 ov;
    __nv_bfloat162* op = (__nv_bfloat162*)&ov;
#pragma unroll
    for (int j = 0; j < 4; j++) {
        float2 a2 = __bfloat1622float2(ap[j]);
        float2 v2 = __bfloat1622float2(vp[j]);
        float u0 = v2.x * ((a2.x - mm[2 * j])     * rr[2 * j]     * wc + bc);
        float u1 = v2.y * ((a2.y - mm[2 * j + 1]) * rr[2 * j + 1] * wc + bc);
        __nv_bfloat162 t;
        t.x = __float2bfloat16(u0);
        t.y = __float2bfloat16(u1);
        op[j] = t;
    }
    *(uint4*)(uo + idx) = ov;
}

// ---------------- launch ----------------
extern "C" void kernel_launch(void* const* d_in, const int* in_sizes, int n_in,
                              void* d_out, int out_size)
{
    const float* x      = (const float*)d_in[0];
    const float* n1w    = (const float*)d_in[1];
    const float* n1b    = (const float*)d_in[2];
    const float* w_h1   = (const float*)d_in[3];
    const float* w_dw1  = (const float*)d_in[4];
    const float* n2w    = (const float*)d_in[5];
    const float* n2b    = (const float*)d_in[6];
    const float* w_p1   = (const float*)d_in[7];
    const float* n3w    = (const float*)d_in[8];
    const float* n3b    = (const float*)d_in[9];
    const float* w_h2   = (const float*)d_in[10];
    const float* b_h2   = (const float*)d_in[11];
    const float* w_dw2  = (const float*)d_in[12];
    const float* w_p2   = (const float*)d_in[13];
    const float* scale1 = (const float*)d_in[14];
    const float* scale2 = (const float*)d_in[15];

    void *p_hidden, *p_qkv, *p_attn, *p_u, *p_x1, *p_h2, *p_g;
    void *p_W1p, *p_S1, *p_B1, *p_W2p, *p_S2, *p_B2;
    cudaGetSymbolAddress(&p_hidden, g_hidden);
    cudaGetSymbolAddress(&p_qkv,    g_qkv);
    cudaGetSymbolAddress(&p_attn,   g_attn);
    cudaGetSymbolAddress(&p_u,      g_u);
    cudaGetSymbolAddress(&p_x1,     g_x1);
    cudaGetSymbolAddress(&p_h2,     g_h2buf);
    cudaGetSymbolAddress(&p_g,      g_gbuf);
    cudaGetSymbolAddress(&p_W1p,    g_W1p);
    cudaGetSymbolAddress(&p_S1,     g_S1);
    cudaGetSymbolAddress(&p_B1,     g_B1);
    cudaGetSymbolAddress(&p_W2p,    g_W2p);
    cudaGetSymbolAddress(&p_S2,     g_S2);
    cudaGetSymbolAddress(&p_B2,     g_B2);

    // 1) fold LN weights into GEMM weights
    k_prep<<<8, 128>>>(w_h1, n1w, n1b, w_h2, b_h2, n3w, n3b);
    // 2) LN1 stats on x
    k_stats<<<NTOT / 256, 256>>>(x, nullptr, DIMC, HW, 1);
    // 3) GEMM1 (768x128) with LN epilogue -> hidden
    {
        EpiArgs e = {};
        e.S = (const float*)p_S1; e.Bv = (const float*)p_B1; e.outB = (bf16*)p_hidden;
        k_gemm<float, 0><<<dim3(NTOT / 128, QKVC / 128), 256>>>(
            (const float*)p_W1p, x, HW, 1, DIMC, e);
    }
    // 4) depthwise 3x3 -> qkv
    k_dwconv<<<dim3(IMG / 32, IMG / 8, QKVC * 2), 256>>>(
        (const bf16*)p_hidden, (bf16*)p_qkv, w_dw1);
    // 5) patch circular conv -> attn
    k_attn<<<(2 * DWC * 1024) / 32, 256>>>((const bf16*)p_qkv, (bf16*)p_attn);
    // 6) LN2 stats on attn
    k_stats<<<NTOT / 256, 256>>>(nullptr, (const bf16*)p_attn, DWC, NTOT, 0);
    // 7) u = v * LN2(attn)
    k_mulv<<<(unsigned)(((size_t)DWC * NTOT) / 8 / 256), 256>>>(
        (const bf16*)p_qkv + (size_t)2 * DWC * NTOT, (const bf16*)p_attn,
        (bf16*)p_u, n2w, n2b);
    // 8) GEMM p1 (128x256), epilogue x1 = x + out*scale1
    {
        EpiArgs e = {};
        e.xin = x; e.scale = scale1; e.outF = (float*)p_x1;
        k_gemm<bf16, 1><<<dim3(NTOT / 128, 1), 256>>>(
            w_p1, (const bf16*)p_u, NTOT, 0, DWC, e);
    }
    // 9) LN3 stats on x1
    k_stats<<<NTOT / 256, 256>>>((const float*)p_x1, nullptr, DIMC, NTOT, 0);
    // 10) GEMM h2 (256x128) with LN epilogue (+bias) -> h2
    {
        EpiArgs e = {};
        e.S = (const float*)p_S2; e.Bv = (const float*)p_B2; e.outB = (bf16*)p_h2;
        k_gemm<float, 0><<<dim3(NTOT / 128, DWC / 128), 256>>>(
            (const float*)p_W2p, (const float*)p_x1, NTOT, 0, DIMC, e);
    }
    // 11) depthwise 3x3 on both halves + GLU product -> g
    k_dwconv_glu<<<dim3(IMG / 32, IMG / 8, DIMC * 2), 256>>>(
        (const bf16*)p_h2, (bf16*)p_g, w_dw2);
    // 12) GEMM p2 (128x128), epilogue out = x1 + out*scale2 -> d_out (BCHW)
    {
        EpiArgs e = {};
        e.xin = (const float*)p_x1; e.scale = scale2; e.outF = (float*)d_out;
        k_gemm<bf16, 2><<<dim3(NTOT / 128, 1), 256>>>(
            w_p2, (const bf16*)p_g, NTOT, 0, DIMC, e);
    }
}

// round 16
// speedup vs baseline: 1.0067x; 1.0011x over previous
#include <cuda_runtime.h>
#include <cuda_bf16.h>
#include <stdint.h>

#define IMG   256
#define HW    65536
#define NTOT  131072
#define DIMC  128
#define DWC   256
#define QKVC  768
#define EPSLN 1e-6f

typedef __nv_bfloat16 bf16;

// ---------------- scratch (device globals; no allocations allowed) ----------------
static __device__ bf16  g_hidden[(size_t)QKVC * NTOT];   // 192MB
static __device__ bf16  g_qkv   [(size_t)QKVC * NTOT];   // 192MB
static __device__ bf16  g_attn  [(size_t)DWC  * NTOT];   // 64MB
static __device__ bf16  g_u     [(size_t)DWC  * NTOT];   // 64MB
static __device__ float g_x1    [(size_t)DIMC * NTOT];   // 64MB
static __device__ bf16  g_h2buf [(size_t)DWC  * NTOT];   // 64MB
static __device__ bf16  g_gbuf  [(size_t)DIMC * NTOT];   // 32MB
static __device__ float g_mean[NTOT];
static __device__ float g_rstd[NTOT];
static __device__ float g_W1p[QKVC * DIMC];
static __device__ float g_S1[QKVC];
static __device__ float g_B1[QKVC];
static __device__ float g_W2p[DWC * DIMC];
static __device__ float g_S2[DWC];
static __device__ float g_B2[DWC];

// ---------------- weight folding: W' = W * ln_w, S = rowsum(W'), B = W*ln_b (+bias) ----------------
__global__ void k_prep(const float* __restrict__ w_h1, const float* __restrict__ n1w,
                       const float* __restrict__ n1b,
                       const float* __restrict__ w_h2, const float* __restrict__ b_h2,
                       const float* __restrict__ n3w, const float* __restrict__ n3b)
{
    int o = blockIdx.x * blockDim.x + threadIdx.x;
    if (o < QKVC) {
        float s = 0.f, bb = 0.f;
        for (int c = 0; c < DIMC; c++) {
            float w  = w_h1[o * DIMC + c];
            float wp = w * n1w[c];
            g_W1p[o * DIMC + c] = wp;
            s  += wp;
            bb += w * n1b[c];
        }
        g_S1[o] = s; g_B1[o] = bb;
    } else if (o < QKVC + DWC) {
        int oo = o - QKVC;
        float s = 0.f, bb = b_h2[oo];
        for (int c = 0; c < DIMC; c++) {
            float w  = w_h2[oo * DIMC + c];
            float wp = w * n3w[c];
            g_W2p[oo * DIMC + c] = wp;
            s  += wp;
            bb += w * n3b[c];
        }
        g_S2[oo] = s; g_B2[oo] = bb;
    }
}

// ---------------- per-pixel LN stats (mean, rstd) over channel dim ----------------
__global__ void k_stats(const float* __restrict__ xf, const bf16* __restrict__ xb,
                        int C, int strideC, int bchw)
{
    int n = blockIdx.x * blockDim.x + threadIdx.x;
    size_t base = bchw ? (size_t)(n >> 16) * ((size_t)C * HW) + (size_t)(n & (HW - 1))
                       : (size_t)n;
    float s = 0.f, ss = 0.f;
    if (xf) {
        for (int c = 0; c < C; c++) {
            float v = xf[base + (size_t)c * strideC];
            s += v; ss += v * v;
        }
    } else {
        for (int c = 0; c < C; c++) {
            float v = __bfloat162float(xb[base + (size_t)c * strideC]);
            s += v; ss += v * v;
        }
    }
    float m = s / C;
    g_mean[n] = m;
    g_rstd[n] = rsqrtf(fmaxf(ss / C - m * m, 0.f) + EPSLN);
}

// ---------------- GEMM: out[M,N] = W[M,K] @ A[K,N], 128x128 tile, 8x8/thread ----------------
struct EpiArgs {
    const float* S;      // EPI 0: row sums of folded W
    const float* Bv;     // EPI 0: bias vector
    const float* xin;    // EPI 1/2: residual input
    const float* scale;  // EPI 1/2: per-channel scale
    float*       outF;
    bf16*        outB;
};

template <typename TA, int EPI>
__global__ __launch_bounds__(256, 2)
void k_gemm(const float* __restrict__ W, const TA* __restrict__ A,
            int strideK, int bchwA, int K, EpiArgs ea)
{
    __shared__ float Ws[16][128];
    __shared__ float As[16][128];
    const int tid = threadIdx.x;
    const int tx  = tid & 15;
    const int ty  = tid >> 4;
    const int n0  = blockIdx.x * 128;
    const int m0  = blockIdx.y * 128;
    const size_t abase = bchwA
        ? (size_t)(n0 >> 16) * ((size_t)DIMC * HW) + (size_t)(n0 & (HW - 1))
        : (size_t)n0;
    const float* Wt = W + (size_t)m0 * K;

    float acc[8][8];
#pragma unroll
    for (int r = 0; r < 8; r++)
#pragma unroll
        for (int c = 0; c < 8; c++) acc[r][c] = 0.f;

    for (int k0 = 0; k0 < K; k0 += 16) {
        __syncthreads();
        // W tile 128x16 -> Ws[k][m]
#pragma unroll
        for (int i = 0; i < 2; i++) {
            int f = tid * 2 + i;
            int row = f >> 2;
            int kc  = (f & 3) * 4;
            float4 w4 = *(const float4*)(Wt + (size_t)row * K + (k0 + kc));
            Ws[kc + 0][row] = w4.x;
            Ws[kc + 1][row] = w4.y;
            Ws[kc + 2][row] = w4.z;
            Ws[kc + 3][row] = w4.w;
        }
        // A tile 16x128 -> As[k][n]
        if constexpr (sizeof(TA) == 4) {
#pragma unroll
            for (int i = 0; i < 2; i++) {
                int f = tid * 2 + i;
                int row = f >> 5;
                int c4  = (f & 31) * 4;
                float4 a4 = *(const float4*)((const float*)A + abase +
                                             (size_t)(k0 + row) * strideK + c4);
                *(float4*)&As[row][c4] = a4;
            }
        } else {
            int row = tid >> 4;
            int c8  = (tid & 15) * 8;
            uint4 v = *(const uint4*)((const bf16*)A + abase +
                                      (size_t)(k0 + row) * strideK + c8);
            const __nv_bfloat162* p2 = (const __nv_bfloat162*)&v;
#pragma unroll
            for (int j = 0; j < 4; j++) {
                float2 f2 = __bfloat1622float2(p2[j]);
                As[row][c8 + 2 * j]     = f2.x;
                As[row][c8 + 2 * j + 1] = f2.y;
            }
        }
        __syncthreads();
#pragma unroll
        for (int kk = 0; kk < 16; kk++) {
            float wr[8], ar[8];
            float4 t;
            t = *(const float4*)&Ws[kk][ty * 4];      wr[0]=t.x; wr[1]=t.y; wr[2]=t.z; wr[3]=t.w;
            t = *(const float4*)&Ws[kk][64 + ty * 4]; wr[4]=t.x; wr[5]=t.y; wr[6]=t.z; wr[7]=t.w;
            t = *(const float4*)&As[kk][tx * 4];      ar[0]=t.x; ar[1]=t.y; ar[2]=t.z; ar[3]=t.w;
            t = *(const float4*)&As[kk][64 + tx * 4]; ar[4]=t.x; ar[5]=t.y; ar[6]=t.z; ar[7]=t.w;
#pragma unroll
            for (int r = 0; r < 8; r++)
#pragma unroll
                for (int c = 0; c < 8; c++)
                    acc[r][c] = fmaf(wr[r], ar[c], acc[r][c]);
        }
    }

    int mrow[8], ncol[8];
#pragma unroll
    for (int r = 0; r < 4; r++) { mrow[r] = ty * 4 + r; mrow[r + 4] = 64 + ty * 4 + r; }
#pragma unroll
    for (int c = 0; c < 4; c++) { ncol[c] = tx * 4 + c; ncol[c + 4] = 64 + tx * 4 + c; }

    if constexpr (EPI == 0) {
        // LN-folded epilogue -> bf16 (C,N) buffer
        float mn[8], rn[8];
#pragma unroll
        for (int c = 0; c < 8; c++) {
            int n = n0 + ncol[c];
            mn[c] = g_mean[n];
            rn[c] = g_rstd[n];
        }
#pragma unroll
        for (int r = 0; r < 8; r++) {
            int m = m0 + mrow[r];
            float Sv  = ea.S[m];
            float Bvv = ea.Bv[m];
            size_t ro = (size_t)m * NTOT + n0;
#pragma unroll
            for (int c = 0; c < 8; c += 2) {
                __nv_bfloat162 t2;
                t2.x = __float2bfloat16(rn[c]     * (acc[r][c]     - mn[c]     * Sv) + Bvv);
                t2.y = __float2bfloat16(rn[c + 1] * (acc[r][c + 1] - mn[c + 1] * Sv) + Bvv);
                *(__nv_bfloat162*)(ea.outB + ro + ncol[c]) = t2;
            }
        }
    } else if constexpr (EPI == 1) {
        // x1 = x(BCHW) + acc*scale -> f32 (C,N)
#pragma unroll
        for (int r = 0; r < 8; r++) {
            int m = m0 + mrow[r];
            float sc = ea.scale[m];
#pragma unroll
            for (int c = 0; c < 8; c++) {
                int n = n0 + ncol[c];
                float xv = ea.xin[(size_t)(n >> 16) * ((size_t)DIMC * HW) +
                                  (size_t)m * HW + (n & (HW - 1))];
                ea.outF[(size_t)m * NTOT + n] = xv + acc[r][c] * sc;
            }
        }
    } else {
        // out(BCHW) = x1(C,N) + acc*scale
#pragma unroll
        for (int r = 0; r < 8; r++) {
            int m = m0 + mrow[r];
            float sc = ea.scale[m];
#pragma unroll
            for (int c = 0; c < 8; c++) {
                int n = n0 + ncol[c];
                float xv = ea.xin[(size_t)m * NTOT + n];
                ea.outF[(size_t)(n >> 16) * ((size_t)DIMC * HW) +
                        (size_t)m * HW + (n & (HW - 1))] = xv + acc[r][c] * sc;
            }
        }
    }
}

// ---------------- depthwise 3x3, SAME/zero-pad, (C,B,HW) bf16 ----------------
__global__ __launch_bounds__(256)
void k_dwconv(const bf16* __restrict__ in, bf16* __restrict__ out,
              const float* __restrict__ w)
{
    __shared__ float s[10][34];
    int c  = blockIdx.z >> 1, b = blockIdx.z & 1;
    int x0 = blockIdx.x * 32, y0 = blockIdx.y * 8;
    size_t base = (size_t)c * NTOT + (size_t)b * HW;
    int tid = threadIdx.x;
    for (int i = tid; i < 340; i += 256) {
        int r = i / 34, cc = i % 34;
        int gy = y0 - 1 + r, gx = x0 - 1 + cc;
        float v = 0.f;
        if (gy >= 0 && gy < IMG && gx >= 0 && gx < IMG)
            v = __bfloat162float(in[base + (size_t)gy * IMG + gx]);
        s[r][cc] = v;
    }
    __syncthreads();
    const float* wc = w + c * 9;
    int x = tid & 31, y = tid >> 5;
    float a =
        wc[0]*s[y][x]     + wc[1]*s[y][x+1]     + wc[2]*s[y][x+2] +
        wc[3]*s[y+1][x]   + wc[4]*s[y+1][x+1]   + wc[5]*s[y+1][x+2] +
        wc[6]*s[y+2][x]   + wc[7]*s[y+2][x+1]   + wc[8]*s[y+2][x+2];
    out[base + (size_t)(y0 + y) * IMG + (x0 + x)] = __float2bfloat16(a);
}

// ---------------- FFN: depthwise 3x3 on both halves + GLU product ----------------
__global__ __launch_bounds__(256)
void k_dwconv_glu(const bf16* __restrict__ in, bf16* __restrict__ out,
                  const float* __restrict__ w)
{
    __shared__ float s1[10][34];
    __shared__ float s2[10][34];
    int c  = blockIdx.z >> 1, b = blockIdx.z & 1;
    int x0 = blockIdx.x * 32, y0 = blockIdx.y * 8;
    size_t base1 = (size_t)c * NTOT + (size_t)b * HW;
    size_t base2 = (size_t)(c + DIMC) * NTOT + (size_t)b * HW;
    int tid = threadIdx.x;
    for (int i = tid; i < 340; i += 256) {
        int r = i / 34, cc = i % 34;
        int gy = y0 - 1 + r, gx = x0 - 1 + cc;
        float v1 = 0.f, v2 = 0.f;
        if (gy >= 0 && gy < IMG && gx >= 0 && gx < IMG) {
            size_t o = (size_t)gy * IMG + gx;
            v1 = __bfloat162float(in[base1 + o]);
            v2 = __bfloat162float(in[base2 + o]);
        }
        s1[r][cc] = v1; s2[r][cc] = v2;
    }
    __syncthreads();
    const float* w1 = w + c * 9;
    const float* w2 = w + (c + DIMC) * 9;
    int x = tid & 31, y = tid >> 5;
    float a1 =
        w1[0]*s1[y][x]   + w1[1]*s1[y][x+1]   + w1[2]*s1[y][x+2] +
        w1[3]*s1[y+1][x] + w1[4]*s1[y+1][x+1] + w1[5]*s1[y+1][x+2] +
        w1[6]*s1[y+2][x] + w1[7]*s1[y+2][x+1] + w1[8]*s1[y+2][x+2];
    float a2 =
        w2[0]*s2[y][x]   + w2[1]*s2[y][x+1]   + w2[2]*s2[y][x+2] +
        w2[3]*s2[y+1][x] + w2[4]*s2[y+1][x+1] + w2[5]*s2[y+1][x+2] +
        w2[6]*s2[y+2][x] + w2[7]*s2[y+2][x+1] + w2[8]*s2[y+2][x+2];
    out[base1 + (size_t)(y0 + y) * IMG + (x0 + x)] = __float2bfloat16(a1 * a2);
}

// ---------------- per-8x8-patch circular convolution attn = q (*) k ----------------
__global__ __launch_bounds__(256)
void k_attn(const bf16* __restrict__ qkv, bf16* __restrict__ attn)
{
    __shared__ float sQ[32][8][8];
    __shared__ float sK[32][8][8];
    int tid = threadIdx.x;
    int pl  = tid >> 3, yr = tid & 7;
    int gp  = blockIdx.x * 32 + pl;       // global patch unit: (c,b,py,px)
    int c   = gp >> 11;
    int rem = gp & 2047;
    int b   = rem >> 10;
    int p   = rem & 1023;
    int py  = p >> 5, px = p & 31;
    size_t pix = (size_t)b * HW + (size_t)(py * 8 + yr) * IMG + (size_t)px * 8;
    {
        uint4 qv = *(const uint4*)(qkv + (size_t)c * NTOT + pix);
        uint4 kv = *(const uint4*)(qkv + (size_t)(c + DWC) * NTOT + pix);
        const __nv_bfloat162* qp = (const __nv_bfloat162*)&qv;
        const __nv_bfloat162* kp = (const __nv_bfloat162*)&kv;
#pragma unroll
        for (int j = 0; j < 4; j++) {
            float2 f = __bfloat1622float2(qp[j]);
            sQ[pl][yr][2 * j] = f.x; sQ[pl][yr][2 * j + 1] = f.y;
            f = __bfloat1622float2(kp[j]);
            sK[pl][yr][2 * j] = f.x; sK[pl][yr][2 * j + 1] = f.y;
        }
    }
    __syncthreads();
    float acc[8];
#pragma unroll
    for (int xx = 0; xx < 8; xx++) acc[xx] = 0.f;
#pragma unroll
    for (int u = 0; u < 8; u++) {
        int krow = (yr - u) & 7;
        float qr[8], kr[8];
#pragma unroll
        for (int j = 0; j < 8; j++) qr[j] = sQ[pl][u][j];
#pragma unroll
        for (int j = 0; j < 8; j++) kr[j] = sK[pl][krow][j];
#pragma unroll
        for (int v = 0; v < 8; v++)
#pragma unroll
            for (int xx = 0; xx < 8; xx++)
                acc[xx] = fmaf(qr[v], kr[(xx - v) & 7], acc[xx]);
    }
    uint4 ov;
    __nv_bfloat162* op = (__nv_bfloat162*)&ov;
#pragma unroll
    for (int j = 0; j < 4; j++) {
        __nv_bfloat162 t;
        t.x = __float2bfloat16(acc[2 * j]);
        t.y = __float2bfloat16(acc[2 * j + 1]);
        op[j] = t;
    }
    *(uint4*)(attn + (size_t)c * NTOT + pix) = ov;
}

// ---------------- u = v * LN2(attn) ----------------
__global__ __launch_bounds__(256)
void k_mulv(const bf16* __restrict__ vv, const bf16* __restrict__ at,
            bf16* __restrict__ uo,
            const float* __restrict__ w2, const float* __restrict__ b2)
{
    size_t idx = ((size_t)blockIdx.x * 256 + threadIdx.x) * 8;
    int c = (int)(idx >> 17);           // / NTOT (2^17)
    int n = (int)(idx & (NTOT - 1));
    float wc = w2[c], bc = b2[c];
    uint4 av  = *(const uint4*)(at + idx);
    uint4 vv4 = *(const uint4*)(vv + idx);
    float4 m0 = *(const float4*)&g_mean[n];
    float4 m1 = *(const float4*)&g_mean[n + 4];
    float4 r0 = *(const float4*)&g_rstd[n];
    float4 r1 = *(const float4*)&g_rstd[n + 4];
    float mm[8] = {m0.x, m0.y, m0.z, m0.w, m1.x, m1.y, m1.z, m1.w};
    float rr[8] = {r0.x, r0.y, r0.z, r0.w, r1.x, r1.y, r1.z, r1.w};
    const __nv_bfloat162* ap = (const __nv_bfloat162*)&av;
    const __nv_bfloat162* vp = (const __nv_bfloat162*)&vv4;
    uint4 ov;
    __nv_bfloat162* op = (__nv_bfloat162*)&ov;
#pragma unroll
    for (int j = 0; j < 4; j++) {
        float2 a2 = __bfloat1622float2(ap[j]);
        float2 v2 = __bfloat1622float2(vp[j]);
        float u0 = v2.x * ((a2.x - mm[2 * j])     * rr[2 * j]     * wc + bc);
        float u1 = v2.y * ((a2.y - mm[2 * j + 1]) * rr[2 * j + 1] * wc + bc);
        __nv_bfloat162 t;
        t.x = __float2bfloat16(u0);
        t.y = __float2bfloat16(u1);
        op[j] = t;
    }
    *(uint4*)(uo + idx) = ov;
}

// ---------------- launch ----------------
extern "C" void kernel_launch(void* const* d_in, const int* in_sizes, int n_in,
                              void* d_out, int out_size)
{
    const float* x      = (const float*)d_in[0];
    const float* n1w    = (const float*)d_in[1];
    const float* n1b    = (const float*)d_in[2];
    const float* w_h1   = (const float*)d_in[3];
    const float* w_dw1  = (const float*)d_in[4];
    const float* n2w    = (const float*)d_in[5];
    const float* n2b    = (const float*)d_in[6];
    const float* w_p1   = (const float*)d_in[7];
    const float* n3w    = (const float*)d_in[8];
    const float* n3b    = (const float*)d_in[9];
    const float* w_h2   = (const float*)d_in[10];
    const float* b_h2   = (const float*)d_in[11];
    const float* w_dw2  = (const float*)d_in[12];
    const float* w_p2   = (const float*)d_in[13];
    const float* scale1 = (const float*)d_in[14];
    const float* scale2 = (const float*)d_in[15];

    void *p_hidden, *p_qkv, *p_attn, *p_u, *p_x1, *p_h2, *p_g;
    void *p_W1p, *p_S1, *p_B1, *p_W2p, *p_S2, *p_B2;
    cudaGetSymbolAddress(&p_hidden, g_hidden);
    cudaGetSymbolAddress(&p_qkv,    g_qkv);
    cudaGetSymbolAddress(&p_attn,   g_attn);
    cudaGetSymbolAddress(&p_u,      g_u);
    cudaGetSymbolAddress(&p_x1,     g_x1);
    cudaGetSymbolAddress(&p_h2,     g_h2buf);
    cudaGetSymbolAddress(&p_g,      g_gbuf);
    cudaGetSymbolAddress(&p_W1p,    g_W1p);
    cudaGetSymbolAddress(&p_S1,     g_S1);
    cudaGetSymbolAddress(&p_B1,     g_B1);
    cudaGetSymbolAddress(&p_W2p,    g_W2p);
    cudaGetSymbolAddress(&p_S2,     g_S2);
    cudaGetSymbolAddress(&p_B2,     g_B2);

    // 1) fold LN weights into GEMM weights
    k_prep<<<8, 128>>>(w_h1, n1w, n1b, w_h2, b_h2, n3w, n3b);
    // 2) LN1 stats on x
    k_stats<<<NTOT / 256, 256>>>(x, nullptr, DIMC, HW, 1);
    // 3) GEMM1 (768x128) with LN epilogue -> hidden
    {
        EpiArgs e = {};
        e.S = (const float*)p_S1; e.Bv = (const float*)p_B1; e.outB = (bf16*)p_hidden;
        k_gemm<float, 0><<<dim3(NTOT / 128, QKVC / 128), 256>>>(
            (const float*)p_W1p, x, HW, 1, DIMC, e);
    }
    // 4) depthwise 3x3 -> qkv
    k_dwconv<<<dim3(IMG / 32, IMG / 8, QKVC * 2), 256>>>(
        (const bf16*)p_hidden, (bf16*)p_qkv, w_dw1);
    // 5) patch circular conv -> attn
    k_attn<<<(2 * DWC * 1024) / 32, 256>>>((const bf16*)p_qkv, (bf16*)p_attn);
    // 6) LN2 stats on attn
    k_stats<<<NTOT / 256, 256>>>(nullptr, (const bf16*)p_attn, DWC, NTOT, 0);
    // 7) u = v * LN2(attn)
    k_mulv<<<(unsigned)(((size_t)DWC * NTOT) / 8 / 256), 256>>>(
        (const bf16*)p_qkv + (size_t)2 * DWC * NTOT, (const bf16*)p_attn,
        (bf16*)p_u, n2w, n2b);
    // 8) GEMM p1 (128x256), epilogue x1 = x + out*scale1
    {
        EpiArgs e = {};
        e.xin = x; e.scale = scale1; e.outF = (float*)p_x1;
        k_gemm<bf16, 1><<<dim3(NTOT / 128, 1), 256>>>(
            w_p1, (const bf16*)p_u, NTOT, 0, DWC, e);
    }
    // 9) LN3 stats on x1
    k_stats<<<NTOT / 256, 256>>>((const float*)p_x1, nullptr, DIMC, NTOT, 0);
    // 10) GEMM h2 (256x128) with LN epilogue (+bias) -> h2
    {
        EpiArgs e = {};
        e.S = (const float*)p_S2; e.Bv = (const float*)p_B2; e.outB = (bf16*)p_h2;
        k_gemm<float, 0><<<dim3(NTOT / 128, DWC / 128), 256>>>(
            (const float*)p_W2p, (const float*)p_x1, NTOT, 0, DIMC, e);
    }
    // 11) depthwise 3x3 on both halves + GLU product -> g
    k_dwconv_glu<<<dim3(IMG / 32, IMG / 8, DIMC * 2), 256>>>(
        (const bf16*)p_h2, (bf16*)p_g, w_dw2);
    // 12) GEMM p2 (128x128), epilogue out = x1 + out*scale2 -> d_out (BCHW)
    {
        EpiArgs e = {};
        e.xin = (const float*)p_x1; e.scale = scale2; e.outF = (float*)d_out;
        k_gemm<bf16, 2><<<dim3(NTOT / 128, 1), 256>>>(
            w_p2, (const bf16*)p_g, NTOT, 0, DIMC, e);
    }
}

// round 17
// speedup vs baseline: 1.2103x; 1.2022x over previous
#include <cuda_runtime.h>
#include <cuda_bf16.h>
#include <stdint.h>

#define IMG   256
#define HW    65536
#define NTOT  131072
#define DIMC  128
#define DWC   256
#define QKVC  768
#define EPSLN 1e-6f

typedef __nv_bfloat16 bf16;
typedef unsigned long long ull;

// ---------------- packed f32x2 helpers (sm_103a FFMA2) ----------------
__device__ __forceinline__ void fma2(ull& d, ull a, ull b) {
    asm("fma.rn.f32x2 %0, %1, %2, %0;" : "+l"(d) : "l"(a), "l"(b));
}
__device__ __forceinline__ ull pack2(float x, float y) {
    ull r; asm("mov.b64 %0, {%1, %2};" : "=l"(r) : "f"(x), "f"(y)); return r;
}
__device__ __forceinline__ void unpack2(float& x, float& y, ull v) {
    asm("mov.b64 {%0, %1}, %2;" : "=f"(x), "=f"(y) : "l"(v));
}

// ---------------- scratch (device globals; no allocations allowed) ----------------
static __device__ bf16  g_hidden[(size_t)QKVC * NTOT];
static __device__ bf16  g_qkv   [(size_t)QKVC * NTOT];
static __device__ bf16  g_attn  [(size_t)DWC  * NTOT];
static __device__ bf16  g_u     [(size_t)DWC  * NTOT];
static __device__ float g_x1    [(size_t)DIMC * NTOT];
static __device__ bf16  g_h2buf [(size_t)DWC  * NTOT];
static __device__ bf16  g_gbuf  [(size_t)DIMC * NTOT];
static __device__ float g_mean[NTOT];
static __device__ float g_rstd[NTOT];
static __device__ float g_W1p[QKVC * DIMC];
static __device__ float g_S1[QKVC];
static __device__ float g_B1[QKVC];
static __device__ float g_W2p[DWC * DIMC];
static __device__ float g_S2[DWC];
static __device__ float g_B2[DWC];

// ---------------- weight folding ----------------
__global__ void k_prep(const float* __restrict__ w_h1, const float* __restrict__ n1w,
                       const float* __restrict__ n1b,
                       const float* __restrict__ w_h2, const float* __restrict__ b_h2,
                       const float* __restrict__ n3w, const float* __restrict__ n3b)
{
    int o = blockIdx.x * blockDim.x + threadIdx.x;
    if (o < QKVC) {
        float s = 0.f, bb = 0.f;
        for (int c = 0; c < DIMC; c++) {
            float w  = w_h1[o * DIMC + c];
            float wp = w * n1w[c];
            g_W1p[o * DIMC + c] = wp;
            s  += wp;
            bb += w * n1b[c];
        }
        g_S1[o] = s; g_B1[o] = bb;
    } else if (o < QKVC + DWC) {
        int oo = o - QKVC;
        float s = 0.f, bb = b_h2[oo];
        for (int c = 0; c < DIMC; c++) {
            float w  = w_h2[oo * DIMC + c];
            float wp = w * n3w[c];
            g_W2p[oo * DIMC + c] = wp;
            s  += wp;
            bb += w * n3b[c];
        }
        g_S2[oo] = s; g_B2[oo] = bb;
    }
}

// ---------------- per-pixel LN stats ----------------
__global__ void k_stats(const float* __restrict__ xf, const bf16* __restrict__ xb,
                        int C, int strideC, int bchw)
{
    int n = blockIdx.x * blockDim.x + threadIdx.x;
    size_t base = bchw ? (size_t)(n >> 16) * ((size_t)C * HW) + (size_t)(n & (HW - 1))
                       : (size_t)n;
    float s = 0.f, ss = 0.f;
    if (xf) {
        for (int c = 0; c < C; c++) {
            float v = xf[base + (size_t)c * strideC];
            s += v; ss += v * v;
        }
    } else {
        for (int c = 0; c < C; c++) {
            float v = __bfloat162float(xb[base + (size_t)c * strideC]);
            s += v; ss += v * v;
        }
    }
    float m = s / C;
    g_mean[n] = m;
    g_rstd[n] = rsqrtf(fmaxf(ss / C - m * m, 0.f) + EPSLN);
}

// ---------------- GEMM with FFMA2 core: out[M,N] = W[M,K] @ A[K,N] ----------------
struct EpiArgs {
    const float* S;
    const float* Bv;
    const float* xin;
    const float* scale;
    float*       outF;
    bf16*        outB;
};

template <typename TA, int EPI>
__global__ __launch_bounds__(256, 2)
void k_gemm(const float* __restrict__ W, const TA* __restrict__ A,
            int strideK, int bchwA, int K, EpiArgs ea)
{
    __shared__ float Ws[16][128];
    __shared__ float As[16][128];
    const int tid = threadIdx.x;
    const int tx  = tid & 15;
    const int ty  = tid >> 4;
    const int n0  = blockIdx.x * 128;
    const int m0  = blockIdx.y * 128;
    const size_t abase = bchwA
        ? (size_t)(n0 >> 16) * ((size_t)DIMC * HW) + (size_t)(n0 & (HW - 1))
        : (size_t)n0;
    const float* Wt = W + (size_t)m0 * K;

    ull acc2[8][4];
#pragma unroll
    for (int r = 0; r < 8; r++)
#pragma unroll
        for (int c = 0; c < 4; c++) acc2[r][c] = 0ULL;

    for (int k0 = 0; k0 < K; k0 += 16) {
        __syncthreads();
        // W tile 128x16 -> Ws[k][m]
#pragma unroll
        for (int i = 0; i < 2; i++) {
            int f = tid * 2 + i;
            int row = f >> 2;
            int kc  = (f & 3) * 4;
            float4 w4 = *(const float4*)(Wt + (size_t)row * K + (k0 + kc));
            Ws[kc + 0][row] = w4.x;
            Ws[kc + 1][row] = w4.y;
            Ws[kc + 2][row] = w4.z;
            Ws[kc + 3][row] = w4.w;
        }
        // A tile 16x128 -> As[k][n]
        if constexpr (sizeof(TA) == 4) {
#pragma unroll
            for (int i = 0; i < 2; i++) {
                int f = tid * 2 + i;
                int row = f >> 5;
                int c4  = (f & 31) * 4;
                float4 a4 = *(const float4*)((const float*)A + abase +
                                             (size_t)(k0 + row) * strideK + c4);
                *(float4*)&As[row][c4] = a4;
            }
        } else {
            int row = tid >> 4;
            int c8  = (tid & 15) * 8;
            uint4 v = *(const uint4*)((const bf16*)A + abase +
                                      (size_t)(k0 + row) * strideK + c8);
            const __nv_bfloat162* p2 = (const __nv_bfloat162*)&v;
#pragma unroll
            for (int j = 0; j < 4; j++) {
                float2 f2 = __bfloat1622float2(p2[j]);
                As[row][c8 + 2 * j]     = f2.x;
                As[row][c8 + 2 * j + 1] = f2.y;
            }
        }
        __syncthreads();
#pragma unroll
        for (int kk = 0; kk < 16; kk++) {
            float wr[8];
            float4 t;
            t = *(const float4*)&Ws[kk][ty * 4];      wr[0]=t.x; wr[1]=t.y; wr[2]=t.z; wr[3]=t.w;
            t = *(const float4*)&Ws[kk][64 + ty * 4]; wr[4]=t.x; wr[5]=t.y; wr[6]=t.z; wr[7]=t.w;
            // A pairs: adjacent columns contiguous in smem -> direct 64-bit loads
            ull ap[4];
            {
                ulonglong2 u0 = *(const ulonglong2*)&As[kk][tx * 4];
                ulonglong2 u1 = *(const ulonglong2*)&As[kk][64 + tx * 4];
                ap[0] = u0.x; ap[1] = u0.y; ap[2] = u1.x; ap[3] = u1.y;
            }
#pragma unroll
            for (int r = 0; r < 8; r++) {
                ull wp = pack2(wr[r], wr[r]);
#pragma unroll
                for (int c = 0; c < 4; c++)
                    fma2(acc2[r][c], wp, ap[c]);
            }
        }
    }

    // unpack accumulators
    float acc[8][8];
#pragma unroll
    for (int r = 0; r < 8; r++)
#pragma unroll
        for (int c = 0; c < 4; c++)
            unpack2(acc[r][2 * c], acc[r][2 * c + 1], acc2[r][c]);

    int mrow[8], ncol[8];
#pragma unroll
    for (int r = 0; r < 4; r++) { mrow[r] = ty * 4 + r; mrow[r + 4] = 64 + ty * 4 + r; }
#pragma unroll
    for (int c = 0; c < 4; c++) { ncol[c] = tx * 4 + c; ncol[c + 4] = 64 + tx * 4 + c; }

    if constexpr (EPI == 0) {
        float mn[8], rn[8];
#pragma unroll
        for (int c = 0; c < 8; c++) {
            int n = n0 + ncol[c];
            mn[c] = g_mean[n];
            rn[c] = g_rstd[n];
        }
#pragma unroll
        for (int r = 0; r < 8; r++) {
            int m = m0 + mrow[r];
            float Sv  = ea.S[m];
            float Bvv = ea.Bv[m];
            size_t ro = (size_t)m * NTOT + n0;
#pragma unroll
            for (int c = 0; c < 8; c += 2) {
                __nv_bfloat162 t2;
                t2.x = __float2bfloat16(rn[c]     * (acc[r][c]     - mn[c]     * Sv) + Bvv);
                t2.y = __float2bfloat16(rn[c + 1] * (acc[r][c + 1] - mn[c + 1] * Sv) + Bvv);
                *(__nv_bfloat162*)(ea.outB + ro + ncol[c]) = t2;
            }
        }
    } else if constexpr (EPI == 1) {
#pragma unroll
        for (int r = 0; r < 8; r++) {
            int m = m0 + mrow[r];
            float sc = ea.scale[m];
#pragma unroll
            for (int c = 0; c < 8; c++) {
                int n = n0 + ncol[c];
                float xv = ea.xin[(size_t)(n >> 16) * ((size_t)DIMC * HW) +
                                  (size_t)m * HW + (n & (HW - 1))];
                ea.outF[(size_t)m * NTOT + n] = xv + acc[r][c] * sc;
            }
        }
    } else {
#pragma unroll
        for (int r = 0; r < 8; r++) {
            int m = m0 + mrow[r];
            float sc = ea.scale[m];
#pragma unroll
            for (int c = 0; c < 8; c++) {
                int n = n0 + ncol[c];
                float xv = ea.xin[(size_t)m * NTOT + n];
                ea.outF[(size_t)(n >> 16) * ((size_t)DIMC * HW) +
                        (size_t)m * HW + (n & (HW - 1))] = xv + acc[r][c] * sc;
            }
        }
    }
}

// ---------------- depthwise 3x3, 32x32 tile, 4 outputs/thread (reg sliding) ----------------
__global__ __launch_bounds__(256)
void k_dwconv(const bf16* __restrict__ in, bf16* __restrict__ out,
              const float* __restrict__ w)
{
    __shared__ float s[34][34];
    int c  = blockIdx.z >> 1, b = blockIdx.z & 1;
    int x0 = blockIdx.x * 32, y0 = blockIdx.y * 32;
    size_t base = (size_t)c * NTOT + (size_t)b * HW;
    int tid = threadIdx.x;
    for (int i = tid; i < 34 * 34; i += 256) {
        int r = i / 34, cc = i - r * 34;
        int gy = y0 - 1 + r, gx = x0 - 1 + cc;
        float v = 0.f;
        if ((unsigned)gy < IMG && (unsigned)gx < IMG)
            v = __bfloat162float(in[base + (size_t)gy * IMG + gx]);
        s[r][cc] = v;
    }
    __syncthreads();
    const float* wc = w + c * 9;
    float w0 = wc[0], w1 = wc[1], w2 = wc[2],
          w3 = wc[3], w4 = wc[4], w5 = wc[5],
          w6 = wc[6], w7 = wc[7], w8 = wc[8];
    int x  = tid & 31;
    int yb = (tid >> 5) * 4;
    float a0 = s[yb][x],     a1 = s[yb][x + 1],     a2 = s[yb][x + 2];
    float b0 = s[yb + 1][x], b1 = s[yb + 1][x + 1], b2 = s[yb + 1][x + 2];
    size_t obase = base + (size_t)(y0 + yb) * IMG + (x0 + x);
#pragma unroll
    for (int j = 0; j < 4; j++) {
        float c0 = s[yb + 2 + j][x], c1 = s[yb + 2 + j][x + 1], c2 = s[yb + 2 + j][x + 2];
        float a = w0 * a0 + w1 * a1 + w2 * a2
                + w3 * b0 + w4 * b1 + w5 * b2
                + w6 * c0 + w7 * c1 + w8 * c2;
        out[obase + (size_t)j * IMG] = __float2bfloat16(a);
        a0 = b0; a1 = b1; a2 = b2;
        b0 = c0; b1 = c1; b2 = c2;
    }
}

// ---------------- FFN: depthwise 3x3 on both halves + GLU product ----------------
__global__ __launch_bounds__(256)
void k_dwconv_glu(const bf16* __restrict__ in, bf16* __restrict__ out,
                  const float* __restrict__ w)
{
    __shared__ float s1[34][34];
    __shared__ float s2[34][34];
    int c  = blockIdx.z >> 1, b = blockIdx.z & 1;
    int x0 = blockIdx.x * 32, y0 = blockIdx.y * 32;
    size_t base1 = (size_t)c * NTOT + (size_t)b * HW;
    size_t base2 = (size_t)(c + DIMC) * NTOT + (size_t)b * HW;
    int tid = threadIdx.x;
    for (int i = tid; i < 34 * 34; i += 256) {
        int r = i / 34, cc = i - r * 34;
        int gy = y0 - 1 + r, gx = x0 - 1 + cc;
        float v1 = 0.f, v2 = 0.f;
        if ((unsigned)gy < IMG && (unsigned)gx < IMG) {
            size_t o = (size_t)gy * IMG + gx;
            v1 = __bfloat162float(in[base1 + o]);
            v2 = __bfloat162float(in[base2 + o]);
        }
        s1[r][cc] = v1; s2[r][cc] = v2;
    }
    __syncthreads();
    const float* p1 = w + c * 9;
    const float* p2 = w + (c + DIMC) * 9;
    float u0 = p1[0], u1 = p1[1], u2 = p1[2], u3 = p1[3], u4 = p1[4],
          u5 = p1[5], u6 = p1[6], u7 = p1[7], u8 = p1[8];
    float v0 = p2[0], v1w = p2[1], v2w = p2[2], v3 = p2[3], v4 = p2[4],
          v5 = p2[5], v6 = p2[6], v7 = p2[7], v8 = p2[8];
    int x  = tid & 31;
    int yb = (tid >> 5) * 4;
    float a0 = s1[yb][x],     a1 = s1[yb][x + 1],     a2 = s1[yb][x + 2];
    float b0 = s1[yb + 1][x], b1 = s1[yb + 1][x + 1], b2 = s1[yb + 1][x + 2];
    float e0 = s2[yb][x],     e1 = s2[yb][x + 1],     e2 = s2[yb][x + 2];
    float f0 = s2[yb + 1][x], f1 = s2[yb + 1][x + 1], f2 = s2[yb + 1][x + 2];
    size_t obase = base1 + (size_t)(y0 + yb) * IMG + (x0 + x);
#pragma unroll
    for (int j = 0; j < 4; j++) {
        float c0 = s1[yb + 2 + j][x], c1 = s1[yb + 2 + j][x + 1], c2 = s1[yb + 2 + j][x + 2];
        float g0 = s2[yb + 2 + j][x], g1 = s2[yb + 2 + j][x + 1], g2 = s2[yb + 2 + j][x + 2];
        float r1 = u0 * a0 + u1 * a1 + u2 * a2
                 + u3 * b0 + u4 * b1 + u5 * b2
                 + u6 * c0 + u7 * c1 + u8 * c2;
        float r2 = v0 * e0 + v1w * e1 + v2w * e2
                 + v3 * f0 + v4 * f1 + v5 * f2
                 + v6 * g0 + v7 * g1 + v8 * g2;
        out[obase + (size_t)j * IMG] = __float2bfloat16(r1 * r2);
        a0 = b0; a1 = b1; a2 = b2; b0 = c0; b1 = c1; b2 = c2;
        e0 = f0; e1 = f1; e2 = f2; f0 = g0; f1 = g1; f2 = g2;
    }
}

// ---------------- per-8x8-patch circular convolution attn = q (*) k ----------------
__global__ __launch_bounds__(256)
void k_attn(const bf16* __restrict__ qkv, bf16* __restrict__ attn)
{
    __shared__ float sQ[32][8][8];
    __shared__ float sK[32][8][8];
    int tid = threadIdx.x;
    int pl  = tid >> 3, yr = tid & 7;
    int gp  = blockIdx.x * 32 + pl;
    int c   = gp >> 11;
    int rem = gp & 2047;
    int b   = rem >> 10;
    int p   = rem & 1023;
    int py  = p >> 5, px = p & 31;
    size_t pix = (size_t)b * HW + (size_t)(py * 8 + yr) * IMG + (size_t)px * 8;
    {
        uint4 qv = *(const uint4*)(qkv + (size_t)c * NTOT + pix);
        uint4 kv = *(const uint4*)(qkv + (size_t)(c + DWC) * NTOT + pix);
        const __nv_bfloat162* qp = (const __nv_bfloat162*)&qv;
        const __nv_bfloat162* kp = (const __nv_bfloat162*)&kv;
#pragma unroll
        for (int j = 0; j < 4; j++) {
            float2 f = __bfloat1622float2(qp[j]);
            sQ[pl][yr][2 * j] = f.x; sQ[pl][yr][2 * j + 1] = f.y;
            f = __bfloat1622float2(kp[j]);
            sK[pl][yr][2 * j] = f.x; sK[pl][yr][2 * j + 1] = f.y;
        }
    }
    __syncthreads();
    float acc[8];
#pragma unroll
    for (int xx = 0; xx < 8; xx++) acc[xx] = 0.f;
#pragma unroll
    for (int u = 0; u < 8; u++) {
        int krow = (yr - u) & 7;
        float qr[8], kr[8];
#pragma unroll
        for (int j = 0; j < 8; j++) qr[j] = sQ[pl][u][j];
#pragma unroll
        for (int j = 0; j < 8; j++) kr[j] = sK[pl][krow][j];
#pragma unroll
        for (int v = 0; v < 8; v++)
#pragma unroll
            for (int xx = 0; xx < 8; xx++)
                acc[xx] = fmaf(qr[v], kr[(xx - v) & 7], acc[xx]);
    }
    uint4 ov;
    __nv_bfloat162* op = (__nv_bfloat162*)&ov;
#pragma unroll
    for (int j = 0; j < 4; j++) {
        __nv_bfloat162 t;
        t.x = __float2bfloat16(acc[2 * j]);
        t.y = __float2bfloat16(acc[2 * j + 1]);
        op[j] = t;
    }
    *(uint4*)(attn + (size_t)c * NTOT + pix) = ov;
}

// ---------------- u = v * LN2(attn) ----------------
__global__ __launch_bounds__(256)
void k_mulv(const bf16* __restrict__ vv, const bf16* __restrict__ at,
            bf16* __restrict__ uo,
            const float* __restrict__ w2, const float* __restrict__ b2)
{
    size_t idx = ((size_t)blockIdx.x * 256 + threadIdx.x) * 8;
    int c = (int)(idx >> 17);
    int n = (int)(idx & (NTOT - 1));
    float wc = w2[c], bc = b2[c];
    uint4 av  = *(const uint4*)(at + idx);
    uint4 vv4 = *(const uint4*)(vv + idx);
    float4 m0 = *(const float4*)&g_mean[n];
    float4 m1 = *(const float4*)&g_mean[n + 4];
    float4 r0 = *(const float4*)&g_rstd[n];
    float4 r1 = *(const float4*)&g_rstd[n + 4];
    float mm[8] = {m0.x, m0.y, m0.z, m0.w, m1.x, m1.y, m1.z, m1.w};
    float rr[8] = {r0.x, r0.y, r0.z, r0.w, r1.x, r1.y, r1.z, r1.w};
    const __nv_bfloat162* ap = (const __nv_bfloat162*)&av;
    const __nv_bfloat162* vp = (const __nv_bfloat162*)&vv4;
    uint4 ov;
    __nv_bfloat162* op = (__nv_bfloat162*)&ov;
#pragma unroll
    for (int j = 0; j < 4; j++) {
        float2 a2 = __bfloat1622float2(ap[j]);
        float2 v2 = __bfloat1622float2(vp[j]);
        float u0 = v2.x * ((a2.x - mm[2 * j])     * rr[2 * j]     * wc + bc);
        float u1 = v2.y * ((a2.y - mm[2 * j + 1]) * rr[2 * j + 1] * wc + bc);
        __nv_bfloat162 t;
        t.x = __float2bfloat16(u0);
        t.y = __float2bfloat16(u1);
        op[j] = t;
    }
    *(uint4*)(uo + idx) = ov;
}

// ---------------- launch ----------------
extern "C" void kernel_launch(void* const* d_in, const int* in_sizes, int n_in,
                              void* d_out, int out_size)
{
    const float* x      = (const float*)d_in[0];
    const float* n1w    = (const float*)d_in[1];
    const float* n1b    = (const float*)d_in[2];
    const float* w_h1   = (const float*)d_in[3];
    const float* w_dw1  = (const float*)d_in[4];
    const float* n2w    = (const float*)d_in[5];
    const float* n2b    = (const float*)d_in[6];
    const float* w_p1   = (const float*)d_in[7];
    const float* n3w    = (const float*)d_in[8];
    const float* n3b    = (const float*)d_in[9];
    const float* w_h2   = (const float*)d_in[10];
    const float* b_h2   = (const float*)d_in[11];
    const float* w_dw2  = (const float*)d_in[12];
    const float* w_p2   = (const float*)d_in[13];
    const float* scale1 = (const float*)d_in[14];
    const float* scale2 = (const float*)d_in[15];

    void *p_hidden, *p_qkv, *p_attn, *p_u, *p_x1, *p_h2, *p_g;
    void *p_W1p, *p_S1, *p_B1, *p_W2p, *p_S2, *p_B2;
    cudaGetSymbolAddress(&p_hidden, g_hidden);
    cudaGetSymbolAddress(&p_qkv,    g_qkv);
    cudaGetSymbolAddress(&p_attn,   g_attn);
    cudaGetSymbolAddress(&p_u,      g_u);
    cudaGetSymbolAddress(&p_x1,     g_x1);
    cudaGetSymbolAddress(&p_h2,     g_h2buf);
    cudaGetSymbolAddress(&p_g,      g_gbuf);
    cudaGetSymbolAddress(&p_W1p,    g_W1p);
    cudaGetSymbolAddress(&p_S1,     g_S1);
    cudaGetSymbolAddress(&p_B1,     g_B1);
    cudaGetSymbolAddress(&p_W2p,    g_W2p);
    cudaGetSymbolAddress(&p_S2,     g_S2);
    cudaGetSymbolAddress(&p_B2,     g_B2);

    // 1) fold LN weights into GEMM weights
    k_prep<<<8, 128>>>(w_h1, n1w, n1b, w_h2, b_h2, n3w, n3b);
    // 2) LN1 stats on x
    k_stats<<<NTOT / 256, 256>>>(x, nullptr, DIMC, HW, 1);
    // 3) GEMM1 (768x128) with LN epilogue -> hidden
    {
        EpiArgs e = {};
        e.S = (const float*)p_S1; e.Bv = (const float*)p_B1; e.outB = (bf16*)p_hidden;
        k_gemm<float, 0><<<dim3(NTOT / 128, QKVC / 128), 256>>>(
            (const float*)p_W1p, x, HW, 1, DIMC, e);
    }
    // 4) depthwise 3x3 -> qkv (32x32 tiles)
    k_dwconv<<<dim3(IMG / 32, IMG / 32, QKVC * 2), 256>>>(
        (const bf16*)p_hidden, (bf16*)p_qkv, w_dw1);
    // 5) patch circular conv -> attn
    k_attn<<<(2 * DWC * 1024) / 32, 256>>>((const bf16*)p_qkv, (bf16*)p_attn);
    // 6) LN2 stats on attn
    k_stats<<<NTOT / 256, 256>>>(nullptr, (const bf16*)p_attn, DWC, NTOT, 0);
    // 7) u = v * LN2(attn)
    k_mulv<<<(unsigned)(((size_t)DWC * NTOT) / 8 / 256), 256>>>(
        (const bf16*)p_qkv + (size_t)2 * DWC * NTOT, (const bf16*)p_attn,
        (bf16*)p_u, n2w, n2b);
    // 8) GEMM p1 (128x256), epilogue x1 = x + out*scale1
    {
        EpiArgs e = {};
        e.xin = x; e.scale = scale1; e.outF = (float*)p_x1;
        k_gemm<bf16, 1><<<dim3(NTOT / 128, 1), 256>>>(
            w_p1, (const bf16*)p_u, NTOT, 0, DWC, e);
    }
    // 9) LN3 stats on x1
    k_stats<<<NTOT / 256, 256>>>((const float*)p_x1, nullptr, DIMC, NTOT, 0);
    // 10) GEMM h2 (256x128) with LN epilogue (+bias) -> h2
    {
        EpiArgs e = {};
        e.S = (const float*)p_S2; e.Bv = (const float*)p_B2; e.outB = (bf16*)p_h2;
        k_gemm<float, 0><<<dim3(NTOT / 128, DWC / 128), 256>>>(
            (const float*)p_W2p, (const float*)p_x1, NTOT, 0, DIMC, e);
    }
    // 11) depthwise 3x3 on both halves + GLU product -> g (32x32 tiles)
    k_dwconv_glu<<<dim3(IMG / 32, IMG / 32, DIMC * 2), 256>>>(
        (const bf16*)p_h2, (bf16*)p_g, w_dw2);
    // 12) GEMM p2 (128x128), epilogue out = x1 + out*scale2 -> d_out (BCHW)
    {
        EpiArgs e = {};
        e.xin = (const float*)p_x1; e.scale = scale2; e.outF = (float*)d_out;
        k_gemm<bf16, 2><<<dim3(NTOT / 128, 1), 256>>>(
            w_p2, (const bf16*)p_g, NTOT, 0, DIMC, e);
    }
}